// round 4
// baseline (speedup 1.0000x reference)
#include <cuda_runtime.h>
#include <math.h>

// ---------------- problem constants ----------------
#define B_    4
#define N_    10000
#define E_    160000
#define M_    (B_*N_)        // 40000 rows (b*N + n)
#define CRU   512            // B*128 cols per node for ru path
#define CC_   256            // B*64  cols per node for c  path
#define NC1   576            // 3*128 (ru) + 3*64 (c-input) GEMM1 columns
#define NC2   192            // 3*64 GEMM2 columns
#define MAXD  192            // per-row sort local buffer cap

// ---------------- scratch (static device globals; no runtime alloc) ----------------
__device__ float g_Xru[M_*128];          // concat(inputs,hx), (M,128) row-major
__device__ float g_Pru[3][N_*CRU];       // per-view ru projections, (N, B*128)
__device__ float g_Qc [3][N_*CC_];       // per-view c projections,  (N, B*64)
__device__ float g_g  [M_*64];           // r*hx, (M,64) row-major (GEMM2 A)
__device__ float g_U  [M_*64];           // u gate, (M,64)
__device__ float g_Wbig[128*NC1];        // permuted [W_ru | W_c-input(padded)]
__device__ float g_Wch [64*NC2];         // permuted W_c hidden-half
__device__ int   g_deg[N_];
__device__ int   g_rowptr[N_+1];
__device__ int   g_cursor[N_];
__device__ int   g_tmpeid[E_];
__device__ int   g_csrsrc[E_];
__device__ float g_csrker[E_];

#define FMA2(d,a,b) asm("fma.rn.f32x2 %0, %1, %2, %0;" : "+l"(d) : "l"(a), "l"(b))

// compile-time scratch-buffer selector: 0..2 -> g_Pru[v], 3..5 -> g_Qc[v-3]
template<int ID>
__device__ __forceinline__ float* sel_buf() {
    if constexpr (ID < 3) return g_Pru[ID];
    else                  return g_Qc[ID-3];
}

// ---------------- CSR build (deterministic) ----------------
__global__ void k_zero() {
    int i = blockIdx.x*256 + threadIdx.x;
    if (i < N_) { g_deg[i] = 0; g_cursor[i] = 0; }
}

__global__ void k_count(const int* __restrict__ dstA) {
    int e = blockIdx.x*256 + threadIdx.x;
    if (e < E_) atomicAdd(&g_deg[dstA[e]], 1);
}

__global__ void k_scan() {
    __shared__ int part[1024];
    int t = threadIdx.x;
    int s = 0;
    #pragma unroll
    for (int i = 0; i < 10; i++) { int idx = t*10 + i; if (idx < N_) s += g_deg[idx]; }
    part[t] = s; __syncthreads();
    for (int off = 1; off < 1024; off <<= 1) {
        int v = (t >= off) ? part[t-off] : 0;
        __syncthreads();
        part[t] += v;
        __syncthreads();
    }
    int run = (t == 0) ? 0 : part[t-1];
    #pragma unroll
    for (int i = 0; i < 10; i++) {
        int idx = t*10 + i;
        if (idx < N_) { g_rowptr[idx] = run; run += g_deg[idx]; }
    }
    if (t == 1023) g_rowptr[N_] = part[1023];
}

__global__ void k_fill(const int* __restrict__ dstA) {
    int e = blockIdx.x*256 + threadIdx.x;
    if (e < E_) {
        int d = dstA[e];
        int p = atomicAdd(&g_cursor[d], 1);
        g_tmpeid[g_rowptr[d] + p] = e;
    }
}

// sort edge ids per row ascending -> deterministic FP sum order; emit final CSR
__global__ void k_sortemit(const int* __restrict__ srcA, const float* __restrict__ kerA) {
    int n = blockIdx.x*256 + threadIdx.x;
    if (n >= N_) return;
    int beg = g_rowptr[n], end = g_rowptr[n+1];
    int d = end - beg;
    if (d <= MAXD) {
        int buf[MAXD];
        for (int i = 0; i < d; i++) buf[i] = g_tmpeid[beg+i];
        for (int i = 1; i < d; i++) {
            int key = buf[i]; int j = i-1;
            while (j >= 0 && buf[j] > key) { buf[j+1] = buf[j]; j--; }
            buf[j+1] = key;
        }
        for (int i = 0; i < d; i++) {
            int e = buf[i];
            g_csrsrc[beg+i] = srcA[e];
            g_csrker[beg+i] = kerA[e];
        }
    } else {  // fallback (practically never taken; E/N ~ 16 avg degree)
        for (int i = 1; i < d; i++) {
            int key = g_tmpeid[beg+i]; int j = i-1;
            while (j >= 0 && g_tmpeid[beg+j] > key) { g_tmpeid[beg+j+1] = g_tmpeid[beg+j]; j--; }
            g_tmpeid[beg+j+1] = key;
        }
        for (int i = 0; i < d; i++) {
            int e = g_tmpeid[beg+i];
            g_csrsrc[beg+i] = srcA[e];
            g_csrker[beg+i] = kerA[e];
        }
    }
}

// ---------------- weight permutation ----------------
// g_Wbig[k][c]: c<384: W_ru[v*128+k][o] (v=c>>7,o=c&127)
//              c>=384: k<64 ? W_c[v*128+k][o] : 0   (v=(c-384)>>6, o=(c-384)&63)
// g_Wch[k][c]:  W_c[v*128+64+k][o]  (v=c>>6, o=c&63)
__global__ void k_weights(const float* __restrict__ W_ru, const float* __restrict__ W_c) {
    int i = blockIdx.x*256 + threadIdx.x;
    if (i < 128*NC1) {
        int k = i / NC1, c = i % NC1;
        float v;
        if (c < 384) { int vv = c >> 7, o = c & 127; v = W_ru[(vv*128 + k)*128 + o]; }
        else { int c2 = c - 384; int vv = c2 >> 6, o = c2 & 63;
               v = (k < 64) ? W_c[(vv*128 + k)*64 + o] : 0.f; }
        g_Wbig[i] = v;
    } else if (i < 128*NC1 + 64*NC2) {
        int j = i - 128*NC1;
        int k = j / NC2, c = j % NC2;
        int vv = c >> 6, o = c & 63;
        g_Wch[j] = W_c[(vv*128 + 64 + k)*64 + o];
    }
}

// concat(inputs,hx) -> g_Xru, vectorized float4 (each row: 16+16 float4)
__global__ void k_xru(const float* __restrict__ inputs, const float* __restrict__ hx) {
    int i = blockIdx.x*256 + threadIdx.x;             // over M_*32 float4 slots
    if (i < M_*32) {
        int m = i >> 5, q = i & 31;
        float4 v = (q < 16) ? *(const float4*)&inputs[m*64 + q*4]
                            : *(const float4*)&hx[m*64 + (q-16)*4];
        *(float4*)&g_Xru[m*128 + q*4] = v;
    }
}

// ---------------- SIMT fp32x2 GEMM ----------------
// C(M x NCOL) = A(M x KD) * Bm(KD x NCOL); 256x64 tile, 8x8 microtile.
// MODE 1: A=g_Xru, B=g_Wbig, NCOL=NC1, scatter (=) into g_Pru / g_Qc.
// MODE 2: A=g_g,   B=g_Wch,  NCOL=NC2, accumulate (+=) into g_Qc.
template<int MODE>
__global__ void __launch_bounds__(256) k_gemm() {
    constexpr int KD   = (MODE == 1) ? 128 : 64;
    constexpr int NCOL = (MODE == 1) ? NC1 : NC2;
    const float* __restrict__ A  = (MODE == 1) ? g_Xru  : g_g;
    const float* __restrict__ Bm = (MODE == 1) ? g_Wbig : g_Wch;

    __shared__ __align__(16) float2 As[16][256];   // duplicated (a,a) pairs
    __shared__ __align__(16) float  Bs[16][64];
    const int t  = threadIdx.x;
    const int tx = t & 7, ty = t >> 3;
    const int m0 = blockIdx.x * 256;
    const int cb = blockIdx.y * 64;
    const int mA = m0 + t;

    unsigned long long acc[8][4];
    #pragma unroll
    for (int i = 0; i < 8; i++)
        #pragma unroll
        for (int j = 0; j < 4; j++) acc[i][j] = 0ull;

    const int kr = t >> 4, cq = (t & 15) * 4;

    #pragma unroll
    for (int step = 0; step < KD/16; ++step) {
        int k0 = step*16;
        float4 av[4];
        if (mA < M_) {
            #pragma unroll
            for (int q = 0; q < 4; q++)
                av[q] = *(const float4*)&A[mA*KD + k0 + q*4];
        } else {
            #pragma unroll
            for (int q = 0; q < 4; q++) av[q] = make_float4(0.f,0.f,0.f,0.f);
        }
        float4 bv = *(const float4*)&Bm[(k0 + kr)*NCOL + cb + cq];

        __syncthreads();
        #pragma unroll
        for (int q = 0; q < 4; q++) {
            As[q*4+0][t] = make_float2(av[q].x, av[q].x);
            As[q*4+1][t] = make_float2(av[q].y, av[q].y);
            As[q*4+2][t] = make_float2(av[q].z, av[q].z);
            As[q*4+3][t] = make_float2(av[q].w, av[q].w);
        }
        *(float4*)&Bs[kr][cq] = bv;
        __syncthreads();

        #pragma unroll
        for (int k = 0; k < 16; k++) {
            ulonglong2 a01 = *(const ulonglong2*)&As[k][ty*8 + 0];
            ulonglong2 a23 = *(const ulonglong2*)&As[k][ty*8 + 2];
            ulonglong2 a45 = *(const ulonglong2*)&As[k][ty*8 + 4];
            ulonglong2 a67 = *(const ulonglong2*)&As[k][ty*8 + 6];
            float4 b0 = *(const float4*)&Bs[k][tx*8 + 0];
            float4 b1 = *(const float4*)&Bs[k][tx*8 + 4];
            union { float4 f; unsigned long long u[2]; } ub0, ub1;
            ub0.f = b0; ub1.f = b1;
            unsigned long long aa[8] = {a01.x,a01.y,a23.x,a23.y,a45.x,a45.y,a67.x,a67.y};
            unsigned long long bb[4] = {ub0.u[0], ub0.u[1], ub1.u[0], ub1.u[1]};
            #pragma unroll
            for (int i = 0; i < 8; i++)
                #pragma unroll
                for (int j = 0; j < 4; j++)
                    FMA2(acc[i][j], aa[i], bb[j]);
        }
    }

    // epilogue: scatter to (N, B*ch) layouts
    #pragma unroll
    for (int i = 0; i < 8; i++) {
        int mm = m0 + ty*8 + i;
        if (mm >= M_) continue;
        int bb_ = mm / N_, nn = mm % N_;
        #pragma unroll
        for (int j = 0; j < 4; j++) {
            union { unsigned long long u; float2 f; } r; r.u = acc[i][j];
            int c = cb + tx*8 + j*2;
            if (MODE == 1) {
                if (c < 384) {
                    *(float2*)&g_Pru[c >> 7][nn*CRU + bb_*128 + (c & 127)] = r.f;
                } else {
                    int c2 = c - 384;
                    *(float2*)&g_Qc[c2 >> 6][nn*CC_ + bb_*64 + (c2 & 63)] = r.f;
                }
            } else {
                float2* p = (float2*)&g_Qc[c >> 6][nn*CC_ + bb_*64 + (c & 63)];
                float2 old = *p;
                old.x += r.f.x; old.y += r.f.y;
                *p = old;
            }
        }
    }
}

// ---------------- SpMM: O[n] = Add[n] + sum_{e in row n} ker_e * S[src_e] ----------------
// Buffers chosen at compile time: SID/AID/OID index g_Pru (0..2) / g_Qc (3..5).
template<int COLS, int SID, int AID, int OID>
__global__ void k_spmm() {
    const float* __restrict__ S   = sel_buf<SID>();
    const float* __restrict__ Add = sel_buf<AID>();
    float*       __restrict__ O   = sel_buf<OID>();
    constexpr int GS  = COLS/4;    // threads per row
    constexpr int GPB = 128/GS;    // rows per block
    int row = blockIdx.x*GPB + threadIdx.x/GS;
    int c   = (threadIdx.x % GS)*4;
    if (row >= N_) return;
    int beg = g_rowptr[row], end = g_rowptr[row+1];
    float ax = 0.f, ay = 0.f, az = 0.f, aw = 0.f;
    #pragma unroll 2
    for (int j = beg; j < end; ++j) {
        int   s  = __ldg(&g_csrsrc[j]);
        float kv = __ldg(&g_csrker[j]);
        float4 v = __ldg((const float4*)&S[s*COLS + c]);
        ax = fmaf(kv, v.x, ax);
        ay = fmaf(kv, v.y, ay);
        az = fmaf(kv, v.z, az);
        aw = fmaf(kv, v.w, aw);
    }
    float4 ad = *(const float4*)&Add[row*COLS + c];
    float4 o = make_float4(ax + ad.x, ay + ad.y, az + ad.z, aw + ad.w);
    *(float4*)&O[row*COLS + c] = o;
}

// ---------------- gates / final ----------------
__global__ void k_gate(const float* __restrict__ hx, const float* __restrict__ b_ru) {
    int i = blockIdx.x*256 + threadIdx.x;
    if (i >= M_*64) return;
    int m = i >> 6, o = i & 63;
    int b = m / N_, n = m % N_;
    const float* S = g_Pru[2];        // full ru pre-activation lives here
    int base = n*CRU + b*128 + o;
    float pr = S[base]      + b_ru[o];
    float pu = S[base + 64] + b_ru[64 + o];
    float r = 1.f / (1.f + expf(-pr));
    float u = 1.f / (1.f + expf(-pu));
    float h = hx[i];
    g_g[i] = r * h;
    g_U[i] = u;
}

__global__ void k_final(const float* __restrict__ hx, const float* __restrict__ b_c,
                        float* __restrict__ out) {
    int i = blockIdx.x*256 + threadIdx.x;
    if (i >= M_*64) return;
    int m = i >> 6, o = i & 63;
    int b = m / N_, n = m % N_;
    float pre = g_Qc[2][n*CC_ + b*64 + o] + b_c[o];
    float cc = tanhf(pre);
    float u = g_U[i];
    out[i] = u * hx[i] + (1.f - u) * cc;
}

// ---------------- launch (kernel launches ONLY — nothing else) ----------------
extern "C" void kernel_launch(void* const* d_in, const int* in_sizes, int n_in,
                              void* d_out, int out_size) {
    const float* inputs = (const float*)d_in[0];
    const float* hx     = (const float*)d_in[1];
    const int*   sidx   = (const int*)  d_in[2];
    const float* ker    = (const float*)d_in[3];
    const float* W_ru   = (const float*)d_in[4];
    const float* b_ru   = (const float*)d_in[5];
    const float* W_c    = (const float*)d_in[6];
    const float* b_c    = (const float*)d_in[7];
    float* out = (float*)d_out;
    const int* srcA = sidx;
    const int* dstA = sidx + E_;

    // CSR build (deterministic: per-row edges sorted by edge id)
    k_zero    <<<(N_ + 255)/256, 256>>>();
    k_count   <<<(E_ + 255)/256, 256>>>(dstA);
    k_scan    <<<1, 1024>>>();
    k_fill    <<<(E_ + 255)/256, 256>>>(dstA);
    k_sortemit<<<(N_ + 255)/256, 256>>>(srcA, ker);

    // weight permutation + concat input
    k_weights<<<(128*NC1 + 64*NC2 + 255)/256, 256>>>(W_ru, W_c);
    k_xru    <<<(M_*32 + 255)/256, 256>>>(inputs, hx);

    // GEMM1: Xru @ [Wru_perm | Wc_in_perm] -> Pru[0..2] and input-half of Qc[0..2]
    k_gemm<1><<<dim3((M_ + 255)/256, NC1/64), 256>>>();

    // ru sparse: Pru1 += A*Pru2 ; Pru2 = Pru0 + A*Pru1
    k_spmm<CRU, 2, 1, 1><<<N_,   128>>>();
    k_spmm<CRU, 1, 0, 2><<<N_,   128>>>();

    // gates: r,u ; g = r*hx
    k_gate<<<(M_*64 + 255)/256, 256>>>(hx, b_ru);

    // GEMM2: g @ Wch_perm -> Qc[0..2] +=
    k_gemm<2><<<dim3((M_ + 255)/256, NC2/64), 256>>>();

    // c sparse: Qc1 += A*Qc2 ; Qc2 = Qc0 + A*Qc1
    k_spmm<CC_, 5, 4, 4><<<N_/2, 128>>>();
    k_spmm<CC_, 4, 3, 5><<<N_/2, 128>>>();

    // out = u*hx + (1-u)*tanh(c_pre + b_c)
    k_final<<<(M_*64 + 255)/256, 256>>>(hx, b_c, out);
}

// round 6
// speedup vs baseline: 1.8222x; 1.8222x over previous
#include <cuda_runtime.h>
#include <cuda_bf16.h>
#include <math.h>
#include <cstdint>

// ---------------- problem constants ----------------
#define B_    4
#define N_    10000
#define E_    160000
#define M_    (B_*N_)        // 40000 rows (m = b*N + n)
#define NC1   576            // GEMM1 cols: 3*128 (ru views) + 3*64 (c input views)
#define NC2   192            // GEMM2 cols: 3*64 (c hidden views)
#define MAXD  192            // per-row sort local buffer cap
#define MTILE ((M_ + 127)/128)   // 313 row tiles

// ---------------- scratch (static device globals; no runtime alloc) ----------------
__device__ __nv_bfloat16 g_Xh[M_*128];   // hi(concat(inputs,hx))
__device__ __nv_bfloat16 g_Xl[M_*128];   // lo part
__device__ __nv_bfloat16 g_gh[M_*64];    // hi(r*hx)
__device__ __nv_bfloat16 g_gl[M_*64];
__device__ __nv_bfloat16 g_W1h[NC1*128]; // GEMM1 weights, [c][k]
__device__ __nv_bfloat16 g_W1l[NC1*128];
__device__ __nv_bfloat16 g_W2h[NC2*64];
__device__ __nv_bfloat16 g_W2l[NC2*64];
__device__ float g_Pru[3][M_*128];       // ru view projections, [v][M][128]
__device__ float g_Qc [3][M_*64];        // c  view projections, [v][M][64]
__device__ float g_U  [M_*64];           // u gate
__device__ int   g_deg[N_];
__device__ int   g_rowptr[N_+1];
__device__ int   g_cursor[N_];
__device__ int   g_tmpeid[E_];
__device__ int   g_csrsrc[E_];
__device__ float g_csrker[E_];

// compile-time scratch-buffer selector: 0..2 -> g_Pru[v], 3..5 -> g_Qc[v-3]
template<int ID>
__device__ __forceinline__ float* sel_buf() {
    if constexpr (ID < 3) return g_Pru[ID];
    else                  return g_Qc[ID-3];
}

// ---------------- PTX helpers (baseline ISA only — no sm_103a features) ----------------
__device__ __forceinline__ uint32_t smem_u32(const void* p) {
    uint32_t a;
    asm("{ .reg .u64 t; cvta.to.shared.u64 t, %1; cvt.u32.u64 %0, t; }" : "=r"(a) : "l"(p));
    return a;
}
__device__ __forceinline__ void cp16(uint32_t dst, const void* src, bool full) {
    int sz = full ? 16 : 0;
    asm volatile("cp.async.cg.shared.global [%0], [%1], 16, %2;"
                 :: "r"(dst), "l"(src), "r"(sz) : "memory");
}
#define CP_COMMIT()  asm volatile("cp.async.commit_group;" ::: "memory")
#define CP_WAIT(n)   asm volatile("cp.async.wait_group %0;" :: "n"(n) : "memory")

#define LDMX4(r0,r1,r2,r3,addr) \
    asm volatile("ldmatrix.sync.aligned.m8n8.x4.shared.b16 {%0,%1,%2,%3}, [%4];" \
        : "=r"(r0),"=r"(r1),"=r"(r2),"=r"(r3) : "r"(addr))

#define MMA16816(d, a, b) \
    asm volatile("mma.sync.aligned.m16n8k16.row.col.f32.bf16.bf16.f32 " \
        "{%0,%1,%2,%3}, {%4,%5,%6,%7}, {%8,%9}, {%0,%1,%2,%3};" \
        : "+f"((d)[0]),"+f"((d)[1]),"+f"((d)[2]),"+f"((d)[3]) \
        : "r"((a)[0]),"r"((a)[1]),"r"((a)[2]),"r"((a)[3]), "r"((b)[0]),"r"((b)[1]))

// ---------------- CSR build (deterministic) ----------------
__global__ void k_zero() {
    int i = blockIdx.x*256 + threadIdx.x;
    if (i < N_) { g_deg[i] = 0; g_cursor[i] = 0; }
}
__global__ void k_count(const int* __restrict__ dstA) {
    int e = blockIdx.x*256 + threadIdx.x;
    if (e < E_) atomicAdd(&g_deg[dstA[e]], 1);
}
__global__ void k_scan() {
    __shared__ int part[1024];
    int t = threadIdx.x;
    int s = 0;
    #pragma unroll
    for (int i = 0; i < 10; i++) { int idx = t*10 + i; if (idx < N_) s += g_deg[idx]; }
    part[t] = s; __syncthreads();
    for (int off = 1; off < 1024; off <<= 1) {
        int v = (t >= off) ? part[t-off] : 0;
        __syncthreads(); part[t] += v; __syncthreads();
    }
    int run = (t == 0) ? 0 : part[t-1];
    #pragma unroll
    for (int i = 0; i < 10; i++) {
        int idx = t*10 + i;
        if (idx < N_) { g_rowptr[idx] = run; run += g_deg[idx]; }
    }
    if (t == 1023) g_rowptr[N_] = part[1023];
}
__global__ void k_fill(const int* __restrict__ dstA) {
    int e = blockIdx.x*256 + threadIdx.x;
    if (e < E_) {
        int d = dstA[e];
        int p = atomicAdd(&g_cursor[d], 1);
        g_tmpeid[g_rowptr[d] + p] = e;
    }
}
__global__ void k_sortemit(const int* __restrict__ srcA, const float* __restrict__ kerA) {
    int n = blockIdx.x*256 + threadIdx.x;
    if (n >= N_) return;
    int beg = g_rowptr[n], end = g_rowptr[n+1];
    int d = end - beg;
    if (d <= MAXD) {
        int buf[MAXD];
        for (int i = 0; i < d; i++) buf[i] = g_tmpeid[beg+i];
        for (int i = 1; i < d; i++) {
            int key = buf[i]; int j = i-1;
            while (j >= 0 && buf[j] > key) { buf[j+1] = buf[j]; j--; }
            buf[j+1] = key;
        }
        for (int i = 0; i < d; i++) {
            int e = buf[i];
            g_csrsrc[beg+i] = srcA[e];
            g_csrker[beg+i] = kerA[e];
        }
    } else {
        for (int i = 1; i < d; i++) {
            int key = g_tmpeid[beg+i]; int j = i-1;
            while (j >= 0 && g_tmpeid[beg+j] > key) { g_tmpeid[beg+j+1] = g_tmpeid[beg+j]; j--; }
            g_tmpeid[beg+j+1] = key;
        }
        for (int i = 0; i < d; i++) {
            int e = g_tmpeid[beg+i];
            g_csrsrc[beg+i] = srcA[e];
            g_csrker[beg+i] = kerA[e];
        }
    }
}

// ---------------- conversions ----------------
__device__ __forceinline__ void split_bf16(float a, __nv_bfloat16& h, __nv_bfloat16& l) {
    h = __float2bfloat16(a);
    l = __float2bfloat16(a - __bfloat162float(h));
}

// weights -> transposed [c][k] bf16 hi/lo
__global__ void k_weights(const float* __restrict__ W_ru, const float* __restrict__ W_c) {
    int i = blockIdx.x*256 + threadIdx.x;
    if (i < NC1*128) {
        int c = i / 128, k = i & 127;
        float v;
        if (c < 384) { int vv = c >> 7, o = c & 127; v = W_ru[(vv*128 + k)*128 + o]; }
        else { int c2 = c - 384; int vv = c2 >> 6, o = c2 & 63;
               v = (k < 64) ? W_c[(vv*128 + k)*64 + o] : 0.f; }
        split_bf16(v, g_W1h[i], g_W1l[i]);
    } else if (i < NC1*128 + NC2*64) {
        int j = i - NC1*128;
        int c = j / 64, k = j & 63;
        int vv = c >> 6, o = c & 63;
        float v = W_c[(vv*128 + 64 + k)*64 + o];
        split_bf16(v, g_W2h[j], g_W2l[j]);
    }
}

// concat(inputs,hx) -> bf16 hi/lo
__global__ void k_xru(const float* __restrict__ inputs, const float* __restrict__ hx) {
    int i = blockIdx.x*256 + threadIdx.x;
    if (i < M_*128) {
        int m = i >> 7, k = i & 127;
        float a = (k < 64) ? inputs[m*64 + k] : hx[m*64 + (k-64)];
        split_bf16(a, g_Xh[i], g_Xl[i]);
    }
}

// ---------------- HMMA GEMM (mma.sync bf16 hi/lo split, fp32 accum) ----------------
// MODE 1: C(M x 576) = Xru(M x 128) @ W1t^T -> g_Pru / g_Qc (=)
// MODE 2: C(M x 192) = g(M x 64) @ W2t^T    -> g_Qc (+=)
// CTA tile 128x64, 4 warps each 32x64. 3 passes: (Ah,Bh),(Ah,Bl),(Al,Bh), K chunked at 64.
// SMEM tiles: rows of 128B, 16B-chunk XOR swizzle (chunk ^ (row&7)) -> conflict-free ldmatrix.
template<int MODE>
__global__ void __launch_bounds__(128) k_mma_gemm() {
    constexpr int KD   = (MODE==1) ? 128 : 64;
    constexpr int CH   = KD/64;            // K-chunks per pass
    constexpr int NCH  = 3*CH;             // total chunk iterations
    constexpr int ABYT = 128*64*2;         // 16384 A-chunk bytes
    constexpr int BBYT = 64*64*2;          // 8192  B-chunk bytes
    constexpr int BUF  = ABYT + BBYT;      // 24576; x2 buffers = 49152 (= default max)

    extern __shared__ char dsm[];
    const uint32_t sbase = smem_u32(dsm);

    const int t = threadIdx.x;
    const int w = t >> 5, l = t & 31;
    const int m0 = blockIdx.x*128, cb = blockIdx.y*64;

    const __nv_bfloat16* A0 = (MODE==1) ? g_Xh  : g_gh;
    const __nv_bfloat16* A1 = (MODE==1) ? g_Xl  : g_gl;
    const __nv_bfloat16* B0 = (MODE==1) ? g_W1h : g_W2h;
    const __nv_bfloat16* B1 = (MODE==1) ? g_W1l : g_W2l;

    float acc[2][8][4];
    #pragma unroll
    for (int i = 0; i < 2; i++)
        #pragma unroll
        for (int j = 0; j < 8; j++)
            #pragma unroll
            for (int k = 0; k < 4; k++) acc[i][j][k] = 0.f;

    // ldmatrix per-lane address components
    const int jm = l >> 3, r = l & 7;
    const int a_row_off = (jm & 1)*8 + r;   // + warp*32 + mt*16
    const int a_kcj     = jm >> 1;
    const int b_row_off = (jm >> 1)*8 + r;  // + np*16
    const int b_kcj     = jm & 1;

    auto load_chunk = [&](int ci, int buf) {
        int p = ci / CH, h = ci % CH;
        const __nv_bfloat16* Ap = (p == 2) ? A1 : A0;
        const __nv_bfloat16* Bp = (p == 1) ? B1 : B0;
        uint32_t ab = sbase + buf*BUF;
        uint32_t bb = ab + ABYT;
        int koff = h*64;
        #pragma unroll
        for (int it = 0; it < 8; it++) {        // A: 128 rows x 8 chunks of 16B
            int idx = it*128 + t;
            int row = idx >> 3, c = idx & 7;
            int gm = m0 + row;
            bool ok = gm < M_;
            const void* src = Ap + (size_t)(ok ? gm : m0)*KD + koff + c*8;
            cp16(ab + row*128 + ((c ^ (row & 7))*16), src, ok);
        }
        #pragma unroll
        for (int it = 0; it < 4; it++) {        // B: 64 rows x 8 chunks of 16B
            int idx = it*128 + t;
            int row = idx >> 3, c = idx & 7;
            const void* src = Bp + (size_t)(cb + row)*KD + koff + c*8;
            cp16(bb + row*128 + ((c ^ (row & 7))*16), src, true);
        }
        CP_COMMIT();
    };

    load_chunk(0, 0);
    for (int i = 0; i < NCH; i++) {
        if (i + 1 < NCH) { load_chunk(i+1, (i+1)&1); CP_WAIT(1); }
        else             { CP_WAIT(0); }
        __syncthreads();
        uint32_t ab = sbase + (i&1)*BUF;
        uint32_t bb = ab + ABYT;
        #pragma unroll
        for (int ks = 0; ks < 4; ks++) {
            uint32_t af[2][4];
            #pragma unroll
            for (int mt = 0; mt < 2; mt++) {
                int row = w*32 + mt*16 + a_row_off;
                uint32_t addr = ab + row*128 + (((ks*2 + a_kcj) ^ r) * 16);
                LDMX4(af[mt][0], af[mt][1], af[mt][2], af[mt][3], addr);
            }
            uint32_t bf[8][2];
            #pragma unroll
            for (int np = 0; np < 4; np++) {
                int row = np*16 + b_row_off;
                uint32_t addr = bb + row*128 + (((ks*2 + b_kcj) ^ r) * 16);
                uint32_t q0, q1, q2, q3;
                LDMX4(q0, q1, q2, q3, addr);
                bf[2*np][0]   = q0; bf[2*np][1]   = q1;
                bf[2*np+1][0] = q2; bf[2*np+1][1] = q3;
            }
            #pragma unroll
            for (int mt = 0; mt < 2; mt++)
                #pragma unroll
                for (int nt = 0; nt < 8; nt++)
                    MMA16816(acc[mt][nt], af[mt], bf[nt]);
        }
        __syncthreads();
    }

    // epilogue: direct float2 stores to view buffers
    float* dstBuf; int dstride;
    if (MODE == 1) {
        if (cb < 384) { dstBuf = g_Pru[cb >> 7] + (cb & 127); dstride = 128; }
        else          { dstBuf = g_Qc[(cb - 384) >> 6];       dstride = 64;  }
    } else {
        dstBuf = g_Qc[blockIdx.y]; dstride = 64;
    }
    const int g = l >> 2, t4 = l & 3;
    #pragma unroll
    for (int mt = 0; mt < 2; mt++) {
        int row0 = m0 + w*32 + mt*16 + g;
        #pragma unroll
        for (int nt = 0; nt < 8; nt++) {
            int col = nt*8 + t4*2;
            if (row0 < M_) {
                float* p = dstBuf + (size_t)row0*dstride + col;
                float2 v = make_float2(acc[mt][nt][0], acc[mt][nt][1]);
                if (MODE == 2) { float2 o = *(float2*)p; v.x += o.x; v.y += o.y; }
                *(float2*)p = v;
            }
            if (row0 + 8 < M_) {
                float* p = dstBuf + (size_t)(row0 + 8)*dstride + col;
                float2 v = make_float2(acc[mt][nt][2], acc[mt][nt][3]);
                if (MODE == 2) { float2 o = *(float2*)p; v.x += o.x; v.y += o.y; }
                *(float2*)p = v;
            }
        }
    }
}

// ---------------- SpMM: O[m] = Add[m] + sum_{e in row n(m)} ker_e * S[bN + src_e] ----------------
template<int COLS, int SID, int AID, int OID>
__global__ void k_spmm() {
    const float* __restrict__ S   = sel_buf<SID>();
    const float* __restrict__ Add = sel_buf<AID>();
    float*       __restrict__ O   = sel_buf<OID>();
    constexpr int GS  = COLS/4;
    constexpr int GPB = 128/GS;
    int m = blockIdx.x*GPB + threadIdx.x/GS;
    int c = (threadIdx.x % GS)*4;
    if (m >= M_) return;
    int n  = m % N_;
    int bN = m - n;
    int beg = g_rowptr[n], end = g_rowptr[n+1];
    float ax = 0.f, ay = 0.f, az = 0.f, aw = 0.f;
    #pragma unroll 2
    for (int j = beg; j < end; ++j) {
        int   s  = __ldg(&g_csrsrc[j]);
        float kv = __ldg(&g_csrker[j]);
        float4 v = __ldg((const float4*)&S[(size_t)(bN + s)*COLS + c]);
        ax = fmaf(kv, v.x, ax);
        ay = fmaf(kv, v.y, ay);
        az = fmaf(kv, v.z, az);
        aw = fmaf(kv, v.w, aw);
    }
    float4 ad = *(const float4*)&Add[(size_t)m*COLS + c];
    float4 o = make_float4(ax + ad.x, ay + ad.y, az + ad.z, aw + ad.w);
    *(float4*)&O[(size_t)m*COLS + c] = o;
}

// ---------------- gates / final ----------------
__global__ void k_gate(const float* __restrict__ hx, const float* __restrict__ b_ru) {
    int i = blockIdx.x*256 + threadIdx.x;
    if (i >= M_*64) return;
    int m = i >> 6, o = i & 63;
    const float* S = g_Pru[2];   // full ru pre-activation, [M][128]
    float pr = S[m*128 + o]      + b_ru[o];
    float pu = S[m*128 + 64 + o] + b_ru[64 + o];
    float r = 1.f / (1.f + expf(-pr));
    float u = 1.f / (1.f + expf(-pu));
    float g = r * hx[i];
    split_bf16(g, g_gh[i], g_gl[i]);
    g_U[i] = u;
}

__global__ void k_final(const float* __restrict__ hx, const float* __restrict__ b_c,
                        float* __restrict__ out) {
    int i = blockIdx.x*256 + threadIdx.x;
    if (i >= M_*64) return;
    int o = i & 63;
    float pre = g_Qc[2][i] + b_c[o];
    float cc = tanhf(pre);
    float u = g_U[i];
    out[i] = u * hx[i] + (1.f - u) * cc;
}

// ---------------- launch (kernel launches only) ----------------
extern "C" void kernel_launch(void* const* d_in, const int* in_sizes, int n_in,
                              void* d_out, int out_size) {
    const float* inputs = (const float*)d_in[0];
    const float* hx     = (const float*)d_in[1];
    const int*   sidx   = (const int*)  d_in[2];
    const float* ker    = (const float*)d_in[3];
    const float* W_ru   = (const float*)d_in[4];
    const float* b_ru   = (const float*)d_in[5];
    const float* W_c    = (const float*)d_in[6];
    const float* b_c    = (const float*)d_in[7];
    float* out = (float*)d_out;
    const int* srcA = sidx;
    const int* dstA = sidx + E_;

    const int DSM = 2*(128*64*2 + 64*64*2);   // 49152 = default dynamic smem max

    // CSR build (deterministic: per-row edges sorted by edge id)
    k_zero    <<<(N_ + 255)/256, 256>>>();
    k_count   <<<(E_ + 255)/256, 256>>>(dstA);
    k_scan    <<<1, 1024>>>();
    k_fill    <<<(E_ + 255)/256, 256>>>(dstA);
    k_sortemit<<<(N_ + 255)/256, 256>>>(srcA, ker);

    // conversions
    k_weights<<<(NC1*128 + NC2*64 + 255)/256, 256>>>(W_ru, W_c);
    k_xru    <<<(M_*128 + 255)/256, 256>>>(inputs, hx);

    // GEMM1 (HMMA): Pru[0..2] and input-half of Qc[0..2]
    k_mma_gemm<1><<<dim3(MTILE, NC1/64), 128, DSM>>>();

    // ru sparse: Pru1 += A*Pru2 ; Pru2 = Pru0 + A*Pru1
    k_spmm<128, 2, 1, 1><<<M_/4, 128>>>();
    k_spmm<128, 1, 0, 2><<<M_/4, 128>>>();

    // gates: r,u ; g = r*hx (bf16 split)
    k_gate<<<(M_*64 + 255)/256, 256>>>(hx, b_ru);

    // GEMM2 (HMMA): Qc[0..2] += g @ W2
    k_mma_gemm<2><<<dim3(MTILE, NC2/64), 128, DSM>>>();

    // c sparse: Qc1 += A*Qc2 ; Qc2 = Qc0 + A*Qc1
    k_spmm<64, 5, 4, 4><<<M_/8, 128>>>();
    k_spmm<64, 4, 3, 5><<<M_/8, 128>>>();

    // out = u*hx + (1-u)*tanh(c_pre + b_c)
    k_final<<<(M_*64 + 255)/256, 256>>>(hx, b_c, out);
}

// round 7
// speedup vs baseline: 2.1986x; 1.2066x over previous
#include <cuda_runtime.h>
#include <cuda_bf16.h>
#include <math.h>
#include <cstdint>
#include <limits.h>

// ---------------- problem constants ----------------
#define B_    4
#define N_    10000
#define E_    160000
#define M_    (B_*N_)        // 40000 rows (m = b*N + n)
#define NC1   576            // GEMM1 cols: 3*128 (ru views) + 3*64 (c input views)
#define NC2   192            // GEMM2 cols: 3*64 (c hidden views)
#define MTILE ((M_ + 127)/128)   // 313 row tiles

// ---------------- scratch (static device globals; no runtime alloc) ----------------
__device__ __nv_bfloat16 g_Xh[M_*128];   // hi(concat(inputs,hx))
__device__ __nv_bfloat16 g_Xl[M_*128];   // lo part
__device__ __nv_bfloat16 g_gh[M_*64];    // hi(r*hx)
__device__ __nv_bfloat16 g_gl[M_*64];
__device__ __nv_bfloat16 g_W1h[NC1*128]; // GEMM1 weights, [c][k]
__device__ __nv_bfloat16 g_W1l[NC1*128];
__device__ __nv_bfloat16 g_W2h[NC2*64];
__device__ __nv_bfloat16 g_W2l[NC2*64];
__device__ float g_Pru[3][M_*128];       // ru view projections, [v][M][128]
__device__ float g_Qc [3][M_*64];        // c  view projections, [v][M][64]
__device__ float g_U  [M_*64];           // u gate
__device__ int   g_deg[N_];
__device__ int   g_rowptr[N_+1];
__device__ int   g_cursor[N_];
__device__ int   g_tmpeid[E_];
__device__ int   g_csrsrc[E_];
__device__ float g_csrker[E_];

// compile-time scratch-buffer selector: 0..2 -> g_Pru[v], 3..5 -> g_Qc[v-3]
template<int ID>
__device__ __forceinline__ float* sel_buf() {
    if constexpr (ID < 3) return g_Pru[ID];
    else                  return g_Qc[ID-3];
}

// ---------------- PTX helpers (baseline ISA only — no sm_103a-suffix features) ----------------
__device__ __forceinline__ uint32_t smem_u32(const void* p) {
    uint32_t a;
    asm("{ .reg .u64 t; cvta.to.shared.u64 t, %1; cvt.u32.u64 %0, t; }" : "=r"(a) : "l"(p));
    return a;
}
__device__ __forceinline__ void cp16(uint32_t dst, const void* src, bool full) {
    int sz = full ? 16 : 0;
    asm volatile("cp.async.cg.shared.global [%0], [%1], 16, %2;"
                 :: "r"(dst), "l"(src), "r"(sz) : "memory");
}
#define CP_COMMIT()  asm volatile("cp.async.commit_group;" ::: "memory")
#define CP_WAIT(n)   asm volatile("cp.async.wait_group %0;" :: "n"(n) : "memory")

#define LDMX4(r0,r1,r2,r3,addr) \
    asm volatile("ldmatrix.sync.aligned.m8n8.x4.shared.b16 {%0,%1,%2,%3}, [%4];" \
        : "=r"(r0),"=r"(r1),"=r"(r2),"=r"(r3) : "r"(addr))

#define MMA16816(d, a, b) \
    asm volatile("mma.sync.aligned.m16n8k16.row.col.f32.bf16.bf16.f32 " \
        "{%0,%1,%2,%3}, {%4,%5,%6,%7}, {%8,%9}, {%0,%1,%2,%3};" \
        : "+f"((d)[0]),"+f"((d)[1]),"+f"((d)[2]),"+f"((d)[3]) \
        : "r"((a)[0]),"r"((a)[1]),"r"((a)[2]),"r"((a)[3]), "r"((b)[0]),"r"((b)[1]))

// ---------------- CSR build (deterministic) ----------------
__global__ void k_zero() {
    int i = blockIdx.x*256 + threadIdx.x;
    if (i < N_) { g_deg[i] = 0; g_cursor[i] = 0; }
}
__global__ void k_count(const int* __restrict__ dstA) {
    int e = blockIdx.x*256 + threadIdx.x;
    if (e < E_) atomicAdd(&g_deg[dstA[e]], 1);
}
__global__ void k_scan() {
    __shared__ int part[1024];
    int t = threadIdx.x;
    int s = 0;
    #pragma unroll
    for (int i = 0; i < 10; i++) { int idx = t*10 + i; if (idx < N_) s += g_deg[idx]; }
    part[t] = s; __syncthreads();
    for (int off = 1; off < 1024; off <<= 1) {
        int v = (t >= off) ? part[t-off] : 0;
        __syncthreads(); part[t] += v; __syncthreads();
    }
    int run = (t == 0) ? 0 : part[t-1];
    #pragma unroll
    for (int i = 0; i < 10; i++) {
        int idx = t*10 + i;
        if (idx < N_) { g_rowptr[idx] = run; run += g_deg[idx]; }
    }
    if (t == 1023) g_rowptr[N_] = part[1023];
}
__global__ void k_fill(const int* __restrict__ dstA) {
    int e = blockIdx.x*256 + threadIdx.x;
    if (e < E_) {
        int d = dstA[e];
        int p = atomicAdd(&g_cursor[d], 1);
        g_tmpeid[g_rowptr[d] + p] = e;
    }
}
// warp rank-sort: one warp per row; edge ids unique -> ranks unique -> deterministic order
__global__ void k_sortemit(const int* __restrict__ srcA, const float* __restrict__ kerA) {
    int warp = (blockIdx.x*256 + threadIdx.x) >> 5;
    int l = threadIdx.x & 31;
    if (warp >= N_) return;
    int n = warp;
    int beg = g_rowptr[n], end = g_rowptr[n+1];
    int d = end - beg;
    if (d <= 64) {
        int e0 = (l      < d) ? g_tmpeid[beg + l]      : INT_MAX;
        int e1 = (32 + l < d) ? g_tmpeid[beg + 32 + l] : INT_MAX;
        int r0 = 0, r1 = 0;
        #pragma unroll
        for (int k = 0; k < 32; k++) {
            int v0 = __shfl_sync(0xFFFFFFFFu, e0, k);
            int v1 = __shfl_sync(0xFFFFFFFFu, e1, k);
            r0 += (v0 < e0) + (v1 < e0);
            r1 += (v0 < e1) + (v1 < e1);
        }
        if (l < d)      { g_csrsrc[beg + r0] = srcA[e0]; g_csrker[beg + r0] = kerA[e0]; }
        if (32 + l < d) { g_csrsrc[beg + r1] = srcA[e1]; g_csrker[beg + r1] = kerA[e1]; }
    } else if (l == 0) {  // fallback (degree ~Poisson(16); effectively never)
        for (int i = 1; i < d; i++) {
            int key = g_tmpeid[beg+i]; int j = i-1;
            while (j >= 0 && g_tmpeid[beg+j] > key) { g_tmpeid[beg+j+1] = g_tmpeid[beg+j]; j--; }
            g_tmpeid[beg+j+1] = key;
        }
        for (int i = 0; i < d; i++) {
            int e = g_tmpeid[beg+i];
            g_csrsrc[beg+i] = srcA[e];
            g_csrker[beg+i] = kerA[e];
        }
    }
}

// ---------------- conversions (merged weights + concat-split) ----------------
__device__ __forceinline__ void split_bf16(float a, __nv_bfloat16& h, __nv_bfloat16& l) {
    h = __float2bfloat16(a);
    l = __float2bfloat16(a - __bfloat162float(h));
}
#define W1SZ (NC1*128)
#define W2SZ (NC2*64)
#define WTOT (W1SZ + W2SZ)
__global__ void k_prep(const float* __restrict__ W_ru, const float* __restrict__ W_c,
                       const float* __restrict__ inputs, const float* __restrict__ hx) {
    int i = blockIdx.x*256 + threadIdx.x;
    if (i < W1SZ) {
        int c = i / 128, k = i & 127;
        float v;
        if (c < 384) { int vv = c >> 7, o = c & 127; v = W_ru[(vv*128 + k)*128 + o]; }
        else { int c2 = c - 384; int vv = c2 >> 6, o = c2 & 63;
               v = (k < 64) ? W_c[(vv*128 + k)*64 + o] : 0.f; }
        split_bf16(v, g_W1h[i], g_W1l[i]);
    } else if (i < WTOT) {
        int j = i - W1SZ;
        int c = j / 64, k = j & 63;
        int vv = c >> 6, o = c & 63;
        float v = W_c[(vv*128 + 64 + k)*64 + o];
        split_bf16(v, g_W2h[j], g_W2l[j]);
    } else if (i < WTOT + M_*128) {
        int j = i - WTOT;
        int m = j >> 7, k = j & 127;
        float a = (k < 64) ? inputs[m*64 + k] : hx[m*64 + (k-64)];
        split_bf16(a, g_Xh[j], g_Xl[j]);
    }
}

// ---------------- HMMA GEMM (mma.sync bf16 hi/lo split, fp32 accum) ----------------
template<int MODE>
__global__ void __launch_bounds__(128) k_mma_gemm() {
    constexpr int KD   = (MODE==1) ? 128 : 64;
    constexpr int CH   = KD/64;
    constexpr int NCH  = 3*CH;
    constexpr int ABYT = 128*64*2;
    constexpr int BBYT = 64*64*2;
    constexpr int BUF  = ABYT + BBYT;      // 24576; x2 = 49152 (default max)

    extern __shared__ char dsm[];
    const uint32_t sbase = smem_u32(dsm);

    const int t = threadIdx.x;
    const int w = t >> 5, l = t & 31;
    const int m0 = blockIdx.x*128, cb = blockIdx.y*64;

    const __nv_bfloat16* A0 = (MODE==1) ? g_Xh  : g_gh;
    const __nv_bfloat16* A1 = (MODE==1) ? g_Xl  : g_gl;
    const __nv_bfloat16* B0 = (MODE==1) ? g_W1h : g_W2h;
    const __nv_bfloat16* B1 = (MODE==1) ? g_W1l : g_W2l;

    float acc[2][8][4];
    #pragma unroll
    for (int i = 0; i < 2; i++)
        #pragma unroll
        for (int j = 0; j < 8; j++)
            #pragma unroll
            for (int k = 0; k < 4; k++) acc[i][j][k] = 0.f;

    const int jm = l >> 3, r = l & 7;
    const int a_row_off = (jm & 1)*8 + r;
    const int a_kcj     = jm >> 1;
    const int b_row_off = (jm >> 1)*8 + r;
    const int b_kcj     = jm & 1;

    auto load_chunk = [&](int ci, int buf) {
        int p = ci / CH, h = ci % CH;
        const __nv_bfloat16* Ap = (p == 2) ? A1 : A0;
        const __nv_bfloat16* Bp = (p == 1) ? B1 : B0;
        uint32_t ab = sbase + buf*BUF;
        uint32_t bb = ab + ABYT;
        int koff = h*64;
        #pragma unroll
        for (int it = 0; it < 8; it++) {
            int idx = it*128 + t;
            int row = idx >> 3, c = idx & 7;
            int gm = m0 + row;
            bool ok = gm < M_;
            const void* src = Ap + (size_t)(ok ? gm : m0)*KD + koff + c*8;
            cp16(ab + row*128 + ((c ^ (row & 7))*16), src, ok);
        }
        #pragma unroll
        for (int it = 0; it < 4; it++) {
            int idx = it*128 + t;
            int row = idx >> 3, c = idx & 7;
            const void* src = Bp + (size_t)(cb + row)*KD + koff + c*8;
            cp16(bb + row*128 + ((c ^ (row & 7))*16), src, true);
        }
        CP_COMMIT();
    };

    load_chunk(0, 0);
    for (int i = 0; i < NCH; i++) {
        if (i + 1 < NCH) { load_chunk(i+1, (i+1)&1); CP_WAIT(1); }
        else             { CP_WAIT(0); }
        __syncthreads();
        uint32_t ab = sbase + (i&1)*BUF;
        uint32_t bb = ab + ABYT;
        #pragma unroll
        for (int ks = 0; ks < 4; ks++) {
            uint32_t af[2][4];
            #pragma unroll
            for (int mt = 0; mt < 2; mt++) {
                int row = w*32 + mt*16 + a_row_off;
                uint32_t addr = ab + row*128 + (((ks*2 + a_kcj) ^ r) * 16);
                LDMX4(af[mt][0], af[mt][1], af[mt][2], af[mt][3], addr);
            }
            uint32_t bf[8][2];
            #pragma unroll
            for (int np = 0; np < 4; np++) {
                int row = np*16 + b_row_off;
                uint32_t addr = bb + row*128 + (((ks*2 + b_kcj) ^ r) * 16);
                uint32_t q0, q1, q2, q3;
                LDMX4(q0, q1, q2, q3, addr);
                bf[2*np][0]   = q0; bf[2*np][1]   = q1;
                bf[2*np+1][0] = q2; bf[2*np+1][1] = q3;
            }
            #pragma unroll
            for (int mt = 0; mt < 2; mt++)
                #pragma unroll
                for (int nt = 0; nt < 8; nt++)
                    MMA16816(acc[mt][nt], af[mt], bf[nt]);
        }
        __syncthreads();
    }

    float* dstBuf; int dstride;
    if (MODE == 1) {
        if (cb < 384) { dstBuf = g_Pru[cb >> 7] + (cb & 127); dstride = 128; }
        else          { dstBuf = g_Qc[(cb - 384) >> 6];       dstride = 64;  }
    } else {
        dstBuf = g_Qc[blockIdx.y]; dstride = 64;
    }
    const int g = l >> 2, t4 = l & 3;
    #pragma unroll
    for (int mt = 0; mt < 2; mt++) {
        int row0 = m0 + w*32 + mt*16 + g;
        #pragma unroll
        for (int nt = 0; nt < 8; nt++) {
            int col = nt*8 + t4*2;
            if (row0 < M_) {
                float* p = dstBuf + (size_t)row0*dstride + col;
                float2 v = make_float2(acc[mt][nt][0], acc[mt][nt][1]);
                if (MODE == 2) { float2 o = *(float2*)p; v.x += o.x; v.y += o.y; }
                *(float2*)p = v;
            }
            if (row0 + 8 < M_) {
                float* p = dstBuf + (size_t)(row0 + 8)*dstride + col;
                float2 v = make_float2(acc[mt][nt][2], acc[mt][nt][3]);
                if (MODE == 2) { float2 o = *(float2*)p; v.x += o.x; v.y += o.y; }
                *(float2*)p = v;
            }
        }
    }
}

// ---------------- SpMM: O[m] = Add[m] + sum_{e in row n(m)} ker_e * S[bN + src_e] ----------------
template<int COLS, int SID, int AID, int OID>
__global__ void k_spmm() {
    const float* __restrict__ S   = sel_buf<SID>();
    const float* __restrict__ Add = sel_buf<AID>();
    float*       __restrict__ O   = sel_buf<OID>();
    constexpr int GS  = COLS/4;
    constexpr int GPB = 128/GS;
    int m = blockIdx.x*GPB + threadIdx.x/GS;
    int c = (threadIdx.x % GS)*4;
    if (m >= M_) return;
    int n  = m % N_;
    int bN = m - n;
    int beg = g_rowptr[n], end = g_rowptr[n+1];
    float ax = 0.f, ay = 0.f, az = 0.f, aw = 0.f;
    #pragma unroll 4
    for (int j = beg; j < end; ++j) {
        int   s  = __ldg(&g_csrsrc[j]);
        float kv = __ldg(&g_csrker[j]);
        float4 v = __ldg((const float4*)&S[(size_t)(bN + s)*COLS + c]);
        ax = fmaf(kv, v.x, ax);
        ay = fmaf(kv, v.y, ay);
        az = fmaf(kv, v.z, az);
        aw = fmaf(kv, v.w, aw);
    }
    float4 ad = *(const float4*)&Add[(size_t)m*COLS + c];
    float4 o = make_float4(ax + ad.x, ay + ad.y, az + ad.z, aw + ad.w);
    *(float4*)&O[(size_t)m*COLS + c] = o;
}

// ---------------- gates / final ----------------
__global__ void k_gate(const float* __restrict__ hx, const float* __restrict__ b_ru) {
    int i = blockIdx.x*256 + threadIdx.x;
    if (i >= M_*64) return;
    int m = i >> 6, o = i & 63;
    const float* S = g_Pru[2];   // full ru pre-activation, [M][128]
    float pr = S[m*128 + o]      + b_ru[o];
    float pu = S[m*128 + 64 + o] + b_ru[64 + o];
    float r = 1.f / (1.f + expf(-pr));
    float u = 1.f / (1.f + expf(-pu));
    float g = r * hx[i];
    split_bf16(g, g_gh[i], g_gl[i]);
    g_U[i] = u;
}

__global__ void k_final(const float* __restrict__ hx, const float* __restrict__ b_c,
                        float* __restrict__ out) {
    int i = blockIdx.x*256 + threadIdx.x;
    if (i >= M_*64) return;
    int o = i & 63;
    float pre = g_Qc[2][i] + b_c[o];
    float cc = tanhf(pre);
    float u = g_U[i];
    out[i] = u * hx[i] + (1.f - u) * cc;
}

// ---------------- launch: fork-join dual-stream (graph-capture legal) ----------------
extern "C" void kernel_launch(void* const* d_in, const int* in_sizes, int n_in,
                              void* d_out, int out_size) {
    const float* inputs = (const float*)d_in[0];
    const float* hx     = (const float*)d_in[1];
    const int*   sidx   = (const int*)  d_in[2];
    const float* ker    = (const float*)d_in[3];
    const float* W_ru   = (const float*)d_in[4];
    const float* b_ru   = (const float*)d_in[5];
    const float* W_c    = (const float*)d_in[6];
    const float* b_c    = (const float*)d_in[7];
    float* out = (float*)d_out;
    const int* srcA = sidx;
    const int* dstA = sidx + E_;

    const int DSM = 2*(128*64*2 + 64*64*2);   // 49152 = default dynamic smem max

    // side stream + events, created once on the first (uncaptured) call.
    // No device memory is allocated; subsequent calls issue only launches/record/wait.
    static cudaStream_t s2 = nullptr;
    static cudaEvent_t evFork = nullptr, evJoin = nullptr;
    if (s2 == nullptr) {
        cudaStreamCreateWithFlags(&s2, cudaStreamNonBlocking);
        cudaEventCreateWithFlags(&evFork, cudaEventDisableTiming);
        cudaEventCreateWithFlags(&evJoin, cudaEventDisableTiming);
    }

    // fork: CSR build chain on s2
    cudaEventRecord(evFork, 0);
    cudaStreamWaitEvent(s2, evFork, 0);
    k_zero    <<<(N_ + 255)/256, 256, 0, s2>>>();
    k_count   <<<(E_ + 255)/256, 256, 0, s2>>>(dstA);
    k_scan    <<<1, 1024, 0, s2>>>();
    k_fill    <<<(E_ + 255)/256, 256, 0, s2>>>(dstA);
    k_sortemit<<<(N_*32 + 255)/256, 256, 0, s2>>>(srcA, ker);
    cudaEventRecord(evJoin, s2);

    // main chain: conversions + GEMM1 (independent of CSR)
    k_prep<<<(WTOT + M_*128 + 255)/256, 256>>>(W_ru, W_c, inputs, hx);
    k_mma_gemm<1><<<dim3(MTILE, NC1/64), 128, DSM>>>();

    // join: SpMM needs both CSR and GEMM1
    cudaStreamWaitEvent(0, evJoin, 0);

    // ru sparse: Pru1 += A*Pru2 ; Pru2 = Pru0 + A*Pru1
    k_spmm<128, 2, 1, 1><<<M_/4, 128>>>();
    k_spmm<128, 1, 0, 2><<<M_/4, 128>>>();

    // gates: r,u ; g = r*hx (bf16 split)
    k_gate<<<(M_*64 + 255)/256, 256>>>(hx, b_ru);

    // GEMM2 (HMMA): Qc[0..2] += g @ W2
    k_mma_gemm<2><<<dim3(MTILE, NC2/64), 128, DSM>>>();

    // c sparse: Qc1 += A*Qc2 ; Qc2 = Qc0 + A*Qc1
    k_spmm<64, 5, 4, 4><<<M_/8, 128>>>();
    k_spmm<64, 4, 3, 5><<<M_/8, 128>>>();

    // out = u*hx + (1-u)*tanh(c_pre + b_c)
    k_final<<<(M_*64 + 255)/256, 256>>>(hx, b_c, out);
}

// round 8
// speedup vs baseline: 2.2349x; 1.0165x over previous
#include <cuda_runtime.h>
#include <cuda_bf16.h>
#include <math.h>
#include <cstdint>
#include <limits.h>

// ---------------- problem constants ----------------
#define B_    4
#define N_    10000
#define E_    160000
#define M_    (B_*N_)        // 40000 rows (m = b*N + n)
#define NC1   576            // GEMM1 cols: 3*128 (ru views) + 3*64 (c input views)
#define NC2   192            // GEMM2 cols: 3*64 (c hidden views)
#define MTILE ((M_ + 127)/128)   // 313 row tiles

// ---------------- scratch (static device globals; no runtime alloc) ----------------
__device__ __nv_bfloat16 g_Xh[M_*128];   // hi(concat(inputs,hx))
__device__ __nv_bfloat16 g_Xl[M_*128];   // lo part
__device__ __nv_bfloat16 g_gh[M_*64];    // hi(r*hx)
__device__ __nv_bfloat16 g_gl[M_*64];
__device__ __nv_bfloat16 g_W1h[NC1*128]; // GEMM1 weights, [c][k]
__device__ __nv_bfloat16 g_W1l[NC1*128];
__device__ __nv_bfloat16 g_W2h[NC2*64];
__device__ __nv_bfloat16 g_W2l[NC2*64];
__device__ float g_Pru[3][M_*128];       // ru fp32 views (view2 slot = pass2 output)
__device__ float g_Qc [3][M_*64];        // c  fp32 views (view2 slot: GEMM1 input-half, then final)
__device__ float g_U  [M_*64];           // u gate
// bf16 gather operands
__device__ __nv_bfloat16 g_Pb2[M_*128];  // bf16(P2) from GEMM1
__device__ __nv_bfloat16 g_Pbt[M_*128];  // bf16(P1 + A P2) from ru pass1
__device__ __nv_bfloat16 g_Qb2[M_*64];   // bf16(Qc2 post-GEMM2)
__device__ __nv_bfloat16 g_Qbt[M_*64];   // bf16(Qc1 + A Qc2) from c pass1
__device__ int   g_deg[N_];
__device__ int   g_rowptr[N_+1];
__device__ int   g_cursor[N_];
__device__ int   g_tmpeid[E_];
__device__ int2  g_csr[E_];              // packed (src, ker bits)

// compile-time selectors
template<int ID>
__device__ __forceinline__ float* sel_buf() {
    if constexpr (ID < 3) return g_Pru[ID];
    else                  return g_Qc[ID-3];
}
template<int ID>
__device__ __forceinline__ __nv_bfloat16* sel_bb() {
    if constexpr (ID == 0) return g_Pb2;
    else if constexpr (ID == 1) return g_Pbt;
    else if constexpr (ID == 2) return g_Qb2;
    else return g_Qbt;
}

// ---------------- PTX helpers (baseline ISA only) ----------------
__device__ __forceinline__ uint32_t smem_u32(const void* p) {
    uint32_t a;
    asm("{ .reg .u64 t; cvta.to.shared.u64 t, %1; cvt.u32.u64 %0, t; }" : "=r"(a) : "l"(p));
    return a;
}
__device__ __forceinline__ void cp16(uint32_t dst, const void* src, bool full) {
    int sz = full ? 16 : 0;
    asm volatile("cp.async.cg.shared.global [%0], [%1], 16, %2;"
                 :: "r"(dst), "l"(src), "r"(sz) : "memory");
}
#define CP_COMMIT()  asm volatile("cp.async.commit_group;" ::: "memory")
#define CP_WAIT(n)   asm volatile("cp.async.wait_group %0;" :: "n"(n) : "memory")

#define LDMX4(r0,r1,r2,r3,addr) \
    asm volatile("ldmatrix.sync.aligned.m8n8.x4.shared.b16 {%0,%1,%2,%3}, [%4];" \
        : "=r"(r0),"=r"(r1),"=r"(r2),"=r"(r3) : "r"(addr))

#define MMA16816(d, a, b) \
    asm volatile("mma.sync.aligned.m16n8k16.row.col.f32.bf16.bf16.f32 " \
        "{%0,%1,%2,%3}, {%4,%5,%6,%7}, {%8,%9}, {%0,%1,%2,%3};" \
        : "+f"((d)[0]),"+f"((d)[1]),"+f"((d)[2]),"+f"((d)[3]) \
        : "r"((a)[0]),"r"((a)[1]),"r"((a)[2]),"r"((a)[3]), "r"((b)[0]),"r"((b)[1]))

// ---------------- CSR build (deterministic) ----------------
__global__ void k_zero() {
    int i = blockIdx.x*256 + threadIdx.x;
    if (i < N_) { g_deg[i] = 0; g_cursor[i] = 0; }
}
__global__ void k_count(const int* __restrict__ dstA) {
    int e = blockIdx.x*256 + threadIdx.x;
    if (e < E_) atomicAdd(&g_deg[dstA[e]], 1);
}
__global__ void k_scan() {
    __shared__ int part[1024];
    int t = threadIdx.x;
    int s = 0;
    #pragma unroll
    for (int i = 0; i < 10; i++) { int idx = t*10 + i; if (idx < N_) s += g_deg[idx]; }
    part[t] = s; __syncthreads();
    for (int off = 1; off < 1024; off <<= 1) {
        int v = (t >= off) ? part[t-off] : 0;
        __syncthreads(); part[t] += v; __syncthreads();
    }
    int run = (t == 0) ? 0 : part[t-1];
    #pragma unroll
    for (int i = 0; i < 10; i++) {
        int idx = t*10 + i;
        if (idx < N_) { g_rowptr[idx] = run; run += g_deg[idx]; }
    }
    if (t == 1023) g_rowptr[N_] = part[1023];
}
__global__ void k_fill(const int* __restrict__ dstA) {
    int e = blockIdx.x*256 + threadIdx.x;
    if (e < E_) {
        int d = dstA[e];
        int p = atomicAdd(&g_cursor[d], 1);
        g_tmpeid[g_rowptr[d] + p] = e;
    }
}
// warp rank-sort: one warp per row; edge ids unique -> deterministic order
__global__ void k_sortemit(const int* __restrict__ srcA, const float* __restrict__ kerA) {
    int warp = (blockIdx.x*256 + threadIdx.x) >> 5;
    int l = threadIdx.x & 31;
    if (warp >= N_) return;
    int n = warp;
    int beg = g_rowptr[n], end = g_rowptr[n+1];
    int d = end - beg;
    if (d <= 64) {
        int e0 = (l      < d) ? g_tmpeid[beg + l]      : INT_MAX;
        int e1 = (32 + l < d) ? g_tmpeid[beg + 32 + l] : INT_MAX;
        int r0 = 0, r1 = 0;
        #pragma unroll
        for (int k = 0; k < 32; k++) {
            int v0 = __shfl_sync(0xFFFFFFFFu, e0, k);
            int v1 = __shfl_sync(0xFFFFFFFFu, e1, k);
            r0 += (v0 < e0) + (v1 < e0);
            r1 += (v0 < e1) + (v1 < e1);
        }
        if (l < d)      g_csr[beg + r0] = make_int2(srcA[e0], __float_as_int(kerA[e0]));
        if (32 + l < d) g_csr[beg + r1] = make_int2(srcA[e1], __float_as_int(kerA[e1]));
    } else if (l == 0) {  // fallback: degree ~Poisson(16); effectively never
        for (int i = 1; i < d; i++) {
            int key = g_tmpeid[beg+i]; int j = i-1;
            while (j >= 0 && g_tmpeid[beg+j] > key) { g_tmpeid[beg+j+1] = g_tmpeid[beg+j]; j--; }
            g_tmpeid[beg+j+1] = key;
        }
        for (int i = 0; i < d; i++) {
            int e = g_tmpeid[beg+i];
            g_csr[beg+i] = make_int2(srcA[e], __float_as_int(kerA[e]));
        }
    }
}

// ---------------- conversions (merged weights + concat-split) ----------------
__device__ __forceinline__ void split_bf16(float a, __nv_bfloat16& h, __nv_bfloat16& l) {
    h = __float2bfloat16(a);
    l = __float2bfloat16(a - __bfloat162float(h));
}
#define W1SZ (NC1*128)
#define W2SZ (NC2*64)
#define WTOT (W1SZ + W2SZ)
__global__ void k_prep(const float* __restrict__ W_ru, const float* __restrict__ W_c,
                       const float* __restrict__ inputs, const float* __restrict__ hx) {
    int i = blockIdx.x*256 + threadIdx.x;
    if (i < W1SZ) {
        int c = i / 128, k = i & 127;
        float v;
        if (c < 384) { int vv = c >> 7, o = c & 127; v = W_ru[(vv*128 + k)*128 + o]; }
        else { int c2 = c - 384; int vv = c2 >> 6, o = c2 & 63;
               v = (k < 64) ? W_c[(vv*128 + k)*64 + o] : 0.f; }
        split_bf16(v, g_W1h[i], g_W1l[i]);
    } else if (i < WTOT) {
        int j = i - W1SZ;
        int c = j / 64, k = j & 63;
        int vv = c >> 6, o = c & 63;
        float v = W_c[(vv*128 + 64 + k)*64 + o];
        split_bf16(v, g_W2h[j], g_W2l[j]);
    } else if (i < WTOT + M_*128) {
        int j = i - WTOT;
        int m = j >> 7, k = j & 127;
        float a = (k < 64) ? inputs[m*64 + k] : hx[m*64 + (k-64)];
        split_bf16(a, g_Xh[j], g_Xl[j]);
    }
}

// ---------------- HMMA GEMM (mma.sync bf16 hi/lo split, fp32 accum) ----------------
template<int MODE>
__global__ void __launch_bounds__(128) k_mma_gemm() {
    constexpr int KD   = (MODE==1) ? 128 : 64;
    constexpr int CH   = KD/64;
    constexpr int NCH  = 3*CH;
    constexpr int ABYT = 128*64*2;
    constexpr int BBYT = 64*64*2;
    constexpr int BUF  = ABYT + BBYT;      // 24576; x2 = 49152 (default max)

    extern __shared__ char dsm[];
    const uint32_t sbase = smem_u32(dsm);

    const int t = threadIdx.x;
    const int w = t >> 5, l = t & 31;
    const int m0 = blockIdx.x*128, cb = blockIdx.y*64;

    const __nv_bfloat16* A0 = (MODE==1) ? g_Xh  : g_gh;
    const __nv_bfloat16* A1 = (MODE==1) ? g_Xl  : g_gl;
    const __nv_bfloat16* B0 = (MODE==1) ? g_W1h : g_W2h;
    const __nv_bfloat16* B1 = (MODE==1) ? g_W1l : g_W2l;

    float acc[2][8][4];
    #pragma unroll
    for (int i = 0; i < 2; i++)
        #pragma unroll
        for (int j = 0; j < 8; j++)
            #pragma unroll
            for (int k = 0; k < 4; k++) acc[i][j][k] = 0.f;

    const int jm = l >> 3, r = l & 7;
    const int a_row_off = (jm & 1)*8 + r;
    const int a_kcj     = jm >> 1;
    const int b_row_off = (jm >> 1)*8 + r;
    const int b_kcj     = jm & 1;

    auto load_chunk = [&](int ci, int buf) {
        int p = ci / CH, h = ci % CH;
        const __nv_bfloat16* Ap = (p == 2) ? A1 : A0;
        const __nv_bfloat16* Bp = (p == 1) ? B1 : B0;
        uint32_t ab = sbase + buf*BUF;
        uint32_t bb = ab + ABYT;
        int koff = h*64;
        #pragma unroll
        for (int it = 0; it < 8; it++) {
            int idx = it*128 + t;
            int row = idx >> 3, c = idx & 7;
            int gm = m0 + row;
            bool ok = gm < M_;
            const void* src = Ap + (size_t)(ok ? gm : m0)*KD + koff + c*8;
            cp16(ab + row*128 + ((c ^ (row & 7))*16), src, ok);
        }
        #pragma unroll
        for (int it = 0; it < 4; it++) {
            int idx = it*128 + t;
            int row = idx >> 3, c = idx & 7;
            const void* src = Bp + (size_t)(cb + row)*KD + koff + c*8;
            cp16(bb + row*128 + ((c ^ (row & 7))*16), src, true);
        }
        CP_COMMIT();
    };

    load_chunk(0, 0);
    for (int i = 0; i < NCH; i++) {
        if (i + 1 < NCH) { load_chunk(i+1, (i+1)&1); CP_WAIT(1); }
        else             { CP_WAIT(0); }
        __syncthreads();
        uint32_t ab = sbase + (i&1)*BUF;
        uint32_t bb = ab + ABYT;
        #pragma unroll
        for (int ks = 0; ks < 4; ks++) {
            uint32_t af[2][4];
            #pragma unroll
            for (int mt = 0; mt < 2; mt++) {
                int row = w*32 + mt*16 + a_row_off;
                uint32_t addr = ab + row*128 + (((ks*2 + a_kcj) ^ r) * 16);
                LDMX4(af[mt][0], af[mt][1], af[mt][2], af[mt][3], addr);
            }
            uint32_t bf[8][2];
            #pragma unroll
            for (int np = 0; np < 4; np++) {
                int row = np*16 + b_row_off;
                uint32_t addr = bb + row*128 + (((ks*2 + b_kcj) ^ r) * 16);
                uint32_t q0, q1, q2, q3;
                LDMX4(q0, q1, q2, q3, addr);
                bf[2*np][0]   = q0; bf[2*np][1]   = q1;
                bf[2*np+1][0] = q2; bf[2*np+1][1] = q3;
            }
            #pragma unroll
            for (int mt = 0; mt < 2; mt++)
                #pragma unroll
                for (int nt = 0; nt < 8; nt++)
                    MMA16816(acc[mt][nt], af[mt], bf[nt]);
        }
        __syncthreads();
    }

    // ---------------- epilogue ----------------
    const int g = l >> 2, t4 = l & 3;
    // dest selection
    float* dstF = nullptr; __nv_bfloat16* dstB = nullptr; int dstride = 128; bool accum = false;
    if (MODE == 1) {
        if (cb < 256)      { dstF = g_Pru[cb >> 7] + (cb & 127); dstride = 128; }
        else if (cb < 384) { dstB = g_Pb2 + (cb & 127);          dstride = 128; }   // bf16-only (gather operand)
        else               { dstF = g_Qc[(cb - 384) >> 6];       dstride = 64;  }
    } else {
        if (blockIdx.y < 2) { dstF = g_Qc[blockIdx.y]; dstride = 64; accum = true; }
        else                { dstB = g_Qb2;            dstride = 64; }              // read fp32 Qc2, add, bf16-only
    }
    #pragma unroll
    for (int mt = 0; mt < 2; mt++) {
        int row0 = m0 + w*32 + mt*16 + g;
        #pragma unroll
        for (int nt = 0; nt < 8; nt++) {
            int col = nt*8 + t4*2;
            #pragma unroll
            for (int half = 0; half < 2; half++) {
                int row = row0 + half*8;
                if (row >= M_) continue;
                float2 v = make_float2(acc[mt][nt][half*2], acc[mt][nt][half*2+1]);
                if (dstB) {
                    if (MODE == 2) {   // add GEMM1 input-half from fp32 Qc2
                        const float2 o = *(const float2*)&g_Qc[2][(size_t)row*64 + col];
                        v.x += o.x; v.y += o.y;
                    }
                    __nv_bfloat162 bp = __float22bfloat162_rn(v);
                    *(__nv_bfloat162*)&dstB[(size_t)row*dstride + col] = bp;
                } else {
                    float* p = dstF + (size_t)row*dstride + col;
                    if (accum) { float2 o = *(float2*)p; v.x += o.x; v.y += o.y; }
                    *(float2*)p = v;
                }
            }
        }
    }
}

// ---------------- SpMM: O[m] = Add[m] + sum_e ker_e * Sb[bN + src_e]  (bf16 gather) ----------------
// SB: bf16 source id; AID: fp32 Add id; OID: output id (bf16 if OBF else fp32)
template<int COLS, int SB, int AID, int OID, bool OBF>
__global__ void __launch_bounds__(256) k_spmm() {
    const __nv_bfloat16* __restrict__ S = sel_bb<SB>();
    const float* __restrict__ Add = sel_buf<AID>();
    constexpr int GS  = COLS/4;     // threads per row (32 ru / 16 c)
    constexpr int GPB = 256/GS;     // rows per block (8 ru / 16 c)
    int m = blockIdx.x*GPB + threadIdx.x/GS;
    int c = (threadIdx.x % GS)*4;
    if (m >= M_) return;
    int n  = m % N_;
    int bN = m - n;
    int beg = g_rowptr[n], end = g_rowptr[n+1];
    float a0 = 0.f, a1 = 0.f, a2 = 0.f, a3 = 0.f;
    #pragma unroll 4
    for (int j = beg; j < end; ++j) {
        int2 ek = __ldg(&g_csr[j]);
        float kv = __int_as_float(ek.y);
        uint2 v = __ldg((const uint2*)&S[(size_t)(bN + ek.x)*COLS + c]);
        float2 f0 = __bfloat1622float2(*(const __nv_bfloat162*)&v.x);
        float2 f1 = __bfloat1622float2(*(const __nv_bfloat162*)&v.y);
        a0 = fmaf(kv, f0.x, a0);
        a1 = fmaf(kv, f0.y, a1);
        a2 = fmaf(kv, f1.x, a2);
        a3 = fmaf(kv, f1.y, a3);
    }
    float4 ad = *(const float4*)&Add[(size_t)m*COLS + c];
    a0 += ad.x; a1 += ad.y; a2 += ad.z; a3 += ad.w;
    if constexpr (OBF) {
        __nv_bfloat16* O = sel_bb<OID>();
        __nv_bfloat162 b0 = __float22bfloat162_rn(make_float2(a0, a1));
        __nv_bfloat162 b1 = __float22bfloat162_rn(make_float2(a2, a3));
        uint2 pk;
        pk.x = *(uint32_t*)&b0;
        pk.y = *(uint32_t*)&b1;
        *(uint2*)&O[(size_t)m*COLS + c] = pk;
    } else {
        float* O = sel_buf<OID>();
        *(float4*)&O[(size_t)m*COLS + c] = make_float4(a0, a1, a2, a3);
    }
}

// ---------------- gates / final ----------------
__global__ void k_gate(const float* __restrict__ hx, const float* __restrict__ b_ru) {
    int i = blockIdx.x*256 + threadIdx.x;
    if (i >= M_*64) return;
    int m = i >> 6, o = i & 63;
    const float* S = g_Pru[2];   // full ru pre-activation, [M][128]
    float pr = S[m*128 + o]      + b_ru[o];
    float pu = S[m*128 + 64 + o] + b_ru[64 + o];
    float r = 1.f / (1.f + expf(-pr));
    float u = 1.f / (1.f + expf(-pu));
    float g = r * hx[i];
    split_bf16(g, g_gh[i], g_gl[i]);
    g_U[i] = u;
}

__global__ void k_final(const float* __restrict__ hx, const float* __restrict__ b_c,
                        float* __restrict__ out) {
    int i = blockIdx.x*256 + threadIdx.x;
    if (i >= M_*64) return;
    int o = i & 63;
    float pre = g_Qc[2][i] + b_c[o];
    float cc = tanhf(pre);
    float u = g_U[i];
    out[i] = u * hx[i] + (1.f - u) * cc;
}

// ---------------- launch: fork-join dual-stream (graph-capture legal) ----------------
extern "C" void kernel_launch(void* const* d_in, const int* in_sizes, int n_in,
                              void* d_out, int out_size) {
    const float* inputs = (const float*)d_in[0];
    const float* hx     = (const float*)d_in[1];
    const int*   sidx   = (const int*)  d_in[2];
    const float* ker    = (const float*)d_in[3];
    const float* W_ru   = (const float*)d_in[4];
    const float* b_ru   = (const float*)d_in[5];
    const float* W_c    = (const float*)d_in[6];
    const float* b_c    = (const float*)d_in[7];
    float* out = (float*)d_out;
    const int* srcA = sidx;
    const int* dstA = sidx + E_;

    const int DSM = 2*(128*64*2 + 64*64*2);   // 49152 = default dynamic smem max

    static cudaStream_t s2 = nullptr;
    static cudaEvent_t evFork = nullptr, evJoin = nullptr;
    if (s2 == nullptr) {
        cudaStreamCreateWithFlags(&s2, cudaStreamNonBlocking);
        cudaEventCreateWithFlags(&evFork, cudaEventDisableTiming);
        cudaEventCreateWithFlags(&evJoin, cudaEventDisableTiming);
    }

    // fork: CSR build chain on s2
    cudaEventRecord(evFork, 0);
    cudaStreamWaitEvent(s2, evFork, 0);
    k_zero    <<<(N_ + 255)/256, 256, 0, s2>>>();
    k_count   <<<(E_ + 255)/256, 256, 0, s2>>>(dstA);
    k_scan    <<<1, 1024, 0, s2>>>();
    k_fill    <<<(E_ + 255)/256, 256, 0, s2>>>(dstA);
    k_sortemit<<<(N_*32 + 255)/256, 256, 0, s2>>>(srcA, ker);
    cudaEventRecord(evJoin, s2);

    // main chain: conversions + GEMM1 (independent of CSR)
    k_prep<<<(WTOT + M_*128 + 255)/256, 256>>>(W_ru, W_c, inputs, hx);
    k_mma_gemm<1><<<dim3(MTILE, NC1/64), 128, DSM>>>();

    // join: SpMM needs both CSR and GEMM1
    cudaStreamWaitEvent(0, evJoin, 0);

    // ru sparse: Pbt = bf16(P1 + A Pb2) ; Pru2 = P0 + A Pbt
    k_spmm<128, 0, 1, 1, true ><<<M_/8,  256>>>();
    k_spmm<128, 1, 0, 2, false><<<M_/8,  256>>>();

    // gates: r,u ; g = r*hx (bf16 split)
    k_gate<<<(M_*64 + 255)/256, 256>>>(hx, b_ru);

    // GEMM2 (HMMA): Qc0/1 += g @ W2 ; Qb2 = bf16(Qc2 + g @ W2_v2)
    k_mma_gemm<2><<<dim3(MTILE, NC2/64), 128, DSM>>>();

    // c sparse: Qbt = bf16(Qc1 + A Qb2) ; Qc2 = Qc0 + A Qbt
    k_spmm<64, 2, 4, 3, true ><<<M_/16, 256>>>();
    k_spmm<64, 3, 3, 5, false><<<M_/16, 256>>>();

    // out = u*hx + (1-u)*tanh(c_pre + b_c)
    k_final<<<(M_*64 + 255)/256, 256>>>(hx, b_c, out);
}